// round 14
// baseline (speedup 1.0000x reference)
#include <cuda_runtime.h>
#include <cuda_fp16.h>
#include <cstdint>

#define Bsz 512
#define Tsz 256
#define Dsz 128
#define Hsz 512
#define GIN 768
#define TB  (Tsz*Bsz)          /* 131072 */
#define BH  (Bsz*Hsz)          /* 262144 */
#define NCTA 128

static const size_t TBH = (size_t)TB * Hsz;   /* 67108864 */

// loop-kernel smem (bytes): WA 64x1040, WB 32x1040, ACT0/ACT1 32x1040, RED 8KB
#define OFF_WA   0u
#define OFF_WB   66560u
#define OFF_ACT0 99840u
#define OFF_ACT1 133120u
#define OFF_RED  166400u
#define SMEM_TOTAL 174592

// precompute-gemm smem: 2 bufs x 2 tiles x (128 rows x 144B)
#define PG_TILE 18432u
#define PG_BUF  36864u
#define PG_SMEM 73728

// ---------------- scratch (__device__ globals: allocation-free) ----------------
__device__ float g_A [201326592];       // 3 x (T*B, H): affine terms (bias incl.)
__device__ float g_gh[67108864];        // (T*B, H): hidden decay gamma_h
__device__ float g_HD[BH];              // hd = gh*h (fp32)
__device__ float g_Z [BH];              // z gate
__device__ __half g_x1h[TB*256];        // [xt|m] fp16
__device__ __half g_dh [TB*128];        // delta fp16
__device__ __half g_hd_h[BH];           // hd fp16
__device__ __half g_rh_h[BH];           // r*hd fp16
__device__ __half g_Wh[3*Hsz*Hsz];      // hidden slices (hi only)
__device__ __half g_W1hh[3*Hsz*256];    // x|m slices (hi only)
__device__ __half g_Wghh[Hsz*128];      // Wgh (hi only)
__device__ unsigned g_bar[512];         // 16 group counters, 128B apart

// ---------------- small helpers ----------------
__device__ __forceinline__ float sigm(float x) { return 1.f / (1.f + expf(-x)); }
__device__ __forceinline__ uint32_t smem_u32(const void* p) {
    uint32_t a;
    asm("{ .reg .u64 t; cvta.to.shared.u64 t, %1; cvt.u32.u64 %0, t; }" : "=r"(a) : "l"(p));
    return a;
}
__device__ __forceinline__ void cpa16(uint32_t dst, const void* src) {
    asm volatile("cp.async.cg.shared.global [%0],[%1],16;" :: "r"(dst), "l"(src));
}
__device__ __forceinline__ void sts16(uint32_t a, uint4 v) {
    asm volatile("st.shared.v4.b32 [%0],{%1,%2,%3,%4};"
                 :: "r"(a), "r"(v.x), "r"(v.y), "r"(v.z), "r"(v.w));
}
__device__ __forceinline__ void ldsm4(uint32_t &r0, uint32_t &r1, uint32_t &r2,
                                      uint32_t &r3, uint32_t addr) {
    asm volatile("ldmatrix.sync.aligned.m8n8.x4.shared.b16 {%0,%1,%2,%3},[%4];"
                 : "=r"(r0), "=r"(r1), "=r"(r2), "=r"(r3) : "r"(addr));
}
__device__ __forceinline__ void mma_f16(float* d, const uint32_t* a,
                                        uint32_t b0, uint32_t b1) {
    asm volatile("mma.sync.aligned.m16n8k16.row.col.f32.f16.f16.f32 "
                 "{%0,%1,%2,%3},{%4,%5,%6,%7},{%8,%9},{%0,%1,%2,%3};"
                 : "+f"(d[0]), "+f"(d[1]), "+f"(d[2]), "+f"(d[3])
                 : "r"(a[0]), "r"(a[1]), "r"(a[2]), "r"(a[3]), "r"(b0), "r"(b1));
}

// ---------------- group barrier primitives (16 CTAs per group) ----------------
__device__ __forceinline__ void arrive_g(int g) {
    __syncthreads();
    if (threadIdx.x == 0) {
        asm volatile("red.release.gpu.global.add.u32 [%0],%1;"
                     :: "l"(g_bar + g * 32), "r"(1u) : "memory");
    }
}
__device__ __forceinline__ void wait_g(int g, unsigned target) {
    if (threadIdx.x == 0) {
        unsigned v;
        do {
            asm volatile("ld.acquire.gpu.global.u32 %0,[%1];"
                         : "=r"(v) : "l"(g_bar + g * 32) : "memory");
        } while (v < target);
    }
    __syncthreads();
}

// ---------------- K0: fused p0 (input decay staging) + weight split + bar -----
__global__ void p0prep_kernel(const float* __restrict__ x,  const float* __restrict__ xl,
                              const float* __restrict__ mk, const float* __restrict__ dl,
                              const float* __restrict__ xmean,
                              const float* __restrict__ Wgx, const float* __restrict__ bgx,
                              const float* __restrict__ Wz, const float* __restrict__ Wr,
                              const float* __restrict__ Wn, const float* __restrict__ Wgh) {
    int bx = blockIdx.x;
    if (bx < 65536) {
        int idx = bx * 256 + threadIdx.x;
        int d   = idx & 127;
        int row = idx >> 7;
        int t   = row >> 9;
        int b   = row & 511;
        size_t xi = ((size_t)b * Tsz + t) * Dsz + d;
        float dv = dl[xi], mv = mk[xi];
        float gx = expf(-fmaxf(0.f, dv * Wgx[d * Dsz + d] + bgx[d]));
        float xt = mv * x[xi] + (1.f - mv) * (gx * xl[xi] + (1.f - gx) * xmean[d]);
        g_x1h[(size_t)row * 256 + d]       = __float2half(xt);
        g_x1h[(size_t)row * 256 + 128 + d] = __float2half(mv);
        g_dh [(size_t)row * 128 + d]       = __float2half(dv);
    } else if (bx < 65536 + 4864) {
        int idx = (bx - 65536) * 256 + threadIdx.x;
        if (idx < 786432) {                 // hidden slices (hi only)
            int k = idx & 511, j = (idx >> 9) & 511, g = idx >> 18;
            const float* W = (g == 0) ? Wz : (g == 1) ? Wr : Wn;
            g_Wh[idx] = __float2half(W[(size_t)j * GIN + 128 + k]);
        } else if (idx < 786432 + 393216) { // x|m slices (hi only)
            int e = idx - 786432;
            int k = e & 255, j = (e >> 8) & 511, g = e >> 17;
            const float* W = (g == 0) ? Wz : (g == 1) ? Wr : Wn;
            int col = (k < 128) ? k : (512 + k);
            g_W1hh[e] = __float2half(W[(size_t)j * GIN + col]);
        } else if (idx < 786432 + 393216 + 65536) {
            int e = idx - 786432 - 393216;
            g_Wghh[e] = __float2half(Wgh[e]);
        }
    } else {
        g_bar[threadIdx.x] = 0u;
        g_bar[threadIdx.x + 256] = 0u;
    }
}

// ---------------- precompute GEMM core (fp16 single-term) ---------------------
template<int KCH>
__device__ __forceinline__ void pg_core(uint32_t sb,
        const __half* __restrict__ Ah, const __half* __restrict__ Bh,
        int row0, int j0, int K, int tid, float d[2][8][4]) {
    #pragma unroll
    for (int mt = 0; mt < 2; mt++)
        #pragma unroll
        for (int nf = 0; nf < 8; nf++)
            #pragma unroll
            for (int i = 0; i < 4; i++) d[mt][nf][i] = 0.f;

    int wid = tid >> 5, l = tid & 31;
    int wr0 = (wid >> 1) * 32;
    int wn0 = (wid & 1) * 64;
    uint32_t aoff = (uint32_t)((wr0 + (l & 15)) * 144 + ((l >> 4) * 8) * 2);
    uint32_t boff = (uint32_t)((wn0 + ((l >> 4) << 3) + (l & 7)) * 144
                               + (((l >> 3) & 1) * 8) * 2);
    int sr = tid >> 3, ss = tid & 7;

    #pragma unroll
    for (int u = 0; u < 4; u++) {
        int r = sr + u * 32;
        uint32_t db = sb + (uint32_t)(r * 144 + ss * 16);
        cpa16(db,           Ah + (size_t)(row0 + r) * K + ss * 8);
        cpa16(db + PG_TILE, Bh + (size_t)(j0 + r) * K + ss * 8);
    }
    asm volatile("cp.async.commit_group;" ::: "memory");

    for (int c = 0; c < KCH; c++) {
        if (c + 1 < KCH) {
            uint32_t bb = sb + ((c + 1) & 1) * PG_BUF;
            #pragma unroll
            for (int u = 0; u < 4; u++) {
                int r = sr + u * 32;
                uint32_t db = bb + (uint32_t)(r * 144 + ss * 16);
                int ko = (c + 1) * 64 + ss * 8;
                cpa16(db,           Ah + (size_t)(row0 + r) * K + ko);
                cpa16(db + PG_TILE, Bh + (size_t)(j0 + r) * K + ko);
            }
            asm volatile("cp.async.commit_group;" ::: "memory");
            asm volatile("cp.async.wait_group 1;" ::: "memory");
        } else {
            asm volatile("cp.async.wait_group 0;" ::: "memory");
        }
        __syncthreads();
        uint32_t bb = sb + (c & 1) * PG_BUF;
        #pragma unroll
        for (int ks = 0; ks < 4; ks++) {
            uint32_t ko = (uint32_t)(ks * 32);
            uint32_t ah[2][4], bh[4][4];
            #pragma unroll
            for (int mt = 0; mt < 2; mt++) {
                uint32_t a = bb + aoff + (uint32_t)(mt * 16 * 144) + ko;
                ldsm4(ah[mt][0], ah[mt][1], ah[mt][2], ah[mt][3], a);
            }
            #pragma unroll
            for (int p = 0; p < 4; p++) {
                uint32_t b = bb + PG_TILE + boff + (uint32_t)(p * 16 * 144) + ko;
                ldsm4(bh[p][0], bh[p][1], bh[p][2], bh[p][3], b);
            }
            #pragma unroll
            for (int p = 0; p < 4; p++)
                #pragma unroll
                for (int mt = 0; mt < 2; mt++) {
                    mma_f16(d[mt][2*p],   ah[mt], bh[p][0], bh[p][1]);
                    mma_f16(d[mt][2*p+1], ah[mt], bh[p][2], bh[p][3]);
                }
        }
        __syncthreads();
    }
}

// ---------------- K1: fused p1m + p2m -----------------------------------------
__global__ __launch_bounds__(256, 2) void p12_kernel(
        const float* __restrict__ bz, const float* __restrict__ br,
        const float* __restrict__ bn, const float* __restrict__ bgh) {
    extern __shared__ char smem[];
    uint32_t sb = smem_u32(smem);
    int tid = threadIdx.x;
    int row0 = blockIdx.y * 128;
    int wid = tid >> 5, l = tid & 31;
    int wr0 = (wid >> 1) * 32, wn0 = (wid & 1) * 64;
    float d[2][8][4];
    if (blockIdx.x < 12) {
        int s = blockIdx.x >> 2;
        int j0 = (blockIdx.x & 3) * 128;
        const float* bias = (s == 0) ? bz : (s == 1) ? br : bn;
        float* out = g_A + (size_t)s * TBH;
        pg_core<4>(sb, g_x1h, g_W1hh + (size_t)s * Hsz * 256, row0, j0, 256, tid, d);
        #pragma unroll
        for (int mt = 0; mt < 2; mt++)
            #pragma unroll
            for (int nf = 0; nf < 8; nf++)
                #pragma unroll
                for (int h = 0; h < 2; h++) {
                    int row = row0 + wr0 + mt * 16 + (l >> 2) + h * 8;
                    int col = j0 + wn0 + nf * 8 + (l & 3) * 2;
                    float2 v;
                    v.x = d[mt][nf][h * 2]     + bias[col];
                    v.y = d[mt][nf][h * 2 + 1] + bias[col + 1];
                    *(float2*)(out + (size_t)row * Hsz + col) = v;
                }
    } else {
        int j0 = (blockIdx.x - 12) * 128;
        pg_core<2>(sb, g_dh, g_Wghh, row0, j0, 128, tid, d);
        #pragma unroll
        for (int mt = 0; mt < 2; mt++)
            #pragma unroll
            for (int nf = 0; nf < 8; nf++)
                #pragma unroll
                for (int h = 0; h < 2; h++) {
                    int row = row0 + wr0 + mt * 16 + (l >> 2) + h * 8;
                    int col = j0 + wn0 + nf * 8 + (l & 3) * 2;
                    float2 v;
                    v.x = expf(-fmaxf(0.f, d[mt][nf][h * 2]     + bgh[col]));
                    v.y = expf(-fmaxf(0.f, d[mt][nf][h * 2 + 1] + bgh[col + 1]));
                    *(float2*)(g_gh + (size_t)row * Hsz + col) = v;
                }
    }
}

__global__ void dummy_kernel() {}

// ---------------- loop helpers ------------------------------------------------
__device__ __forceinline__ void stage32_issue(uint32_t A, const __half* __restrict__ gact,
                                              int r0, int tid) {
    #pragma unroll
    for (int u = 0; u < 4; u++) {
        int i = u * 512 + tid;
        cpa16(A + (uint32_t)((i >> 6) * 1040 + (i & 63) * 16),
              gact + (size_t)(r0 + (i >> 6)) * Hsz + (i & 63) * 8);
    }
    asm volatile("cp.async.commit_group;" ::: "memory");
}

// 16x16 warp-tile fp16 GEMM; 8 accumulator chains
template<int KS>
__device__ __forceinline__ void mma_tileN2(uint32_t sb, uint32_t woff, uint32_t actoff,
                                           int k0, int l, int wr0, int wn0, float d[2][4]) {
    uint32_t Ab = sb + actoff;
    uint32_t aoff = (uint32_t)((wr0 + (l & 15)) * 1040 + ((l >> 4) * 8) * 2 + k0 * 2);
    uint32_t b1o  = (uint32_t)((wn0 + (l & 7)) * 1040 + (l >> 3) * 16 + k0 * 2);
    uint32_t b2o  = b1o + 8 * 1040;
    float c[8][4];
    #pragma unroll
    for (int i = 0; i < 8; i++)
        #pragma unroll
        for (int j = 0; j < 4; j++) c[i][j] = 0.f;
    #pragma unroll
    for (int it = 0; it < KS / 2; it++) {
        uint32_t a0[4], a1[4], b1[4], b2[4];
        ldsm4(a0[0], a0[1], a0[2], a0[3], Ab + aoff + it * 64);
        ldsm4(a1[0], a1[1], a1[2], a1[3], Ab + aoff + it * 64 + 32);
        ldsm4(b1[0], b1[1], b1[2], b1[3], sb + woff + b1o + it * 64);
        ldsm4(b2[0], b2[1], b2[2], b2[3], sb + woff + b2o + it * 64);
        int p = (it & 1) * 4;
        mma_f16(c[p + 0], a0, b1[0], b1[1]);
        mma_f16(c[p + 1], a0, b2[0], b2[1]);
        mma_f16(c[p + 2], a1, b1[2], b1[3]);
        mma_f16(c[p + 3], a1, b2[2], b2[3]);
    }
    #pragma unroll
    for (int i = 0; i < 4; i++) {
        d[0][i] = (c[0][i] + c[2][i]) + (c[4][i] + c[6][i]);
        d[1][i] = (c[1][i] + c[3][i]) + (c[5][i] + c[7][i]);
    }
}

// 16x8 warp-tile fp16 GEMM (phase B); 4 accumulator chains
template<int KS>
__device__ __forceinline__ void mma_tile(uint32_t sb, uint32_t woff, uint32_t actoff,
                                         int k0, int l, int wr0, int wn0, float d[4]) {
    uint32_t Ab = sb + actoff;
    uint32_t aoff = (uint32_t)((wr0 + (l & 15)) * 1040 + ((l >> 4) * 8) * 2 + k0 * 2);
    uint32_t boff = (uint32_t)((wn0 + (l & 7)) * 1040 + (l >> 3) * 16 + k0 * 2);
    float c0[4] = {0,0,0,0}, c1[4] = {0,0,0,0};
    float c2[4] = {0,0,0,0}, c3[4] = {0,0,0,0};
    #pragma unroll
    for (int it = 0; it < KS / 2; it++) {
        uint32_t a0[4], a1[4], b[4];
        ldsm4(a0[0], a0[1], a0[2], a0[3], Ab + aoff + it * 64);
        ldsm4(a1[0], a1[1], a1[2], a1[3], Ab + aoff + it * 64 + 32);
        ldsm4(b[0], b[1], b[2], b[3], sb + woff + boff + it * 64);
        if (it & 1) {
            mma_f16(c2, a0, b[0], b[1]);
            mma_f16(c3, a1, b[2], b[3]);
        } else {
            mma_f16(c0, a0, b[0], b[1]);
            mma_f16(c1, a1, b[2], b[3]);
        }
    }
    #pragma unroll
    for (int i = 0; i < 4; i++) d[i] = (c0[i] + c1[i]) + (c2[i] + c3[i]);
}

// ---------------- phase executors ---------------------------------------------
struct Ctx {
    uint32_t sb; int tid, wid, l;
    int sA, jA0, jB0;
    int widA, wr0A, wn0A, kA0;
    int widB, wr0B, wn0B, kB0;
};

__device__ __forceinline__ void phaseA_exec(const Ctx& c, char* smem, uint32_t actoff,
                                            int g, int t, bool two_pending) {
    int rA0 = g * 32, l = c.l, wid = c.wid;
    const float* At = g_A + (size_t)c.sA * TBH + (size_t)t * BH;
    float2 atv[2][2], hdv[2][2];
    if (wid < 8) {
        #pragma unroll
        for (int nf = 0; nf < 2; nf++)
            #pragma unroll
            for (int h = 0; h < 2; h++) {
                int col = c.jA0 + c.wn0A + nf * 8 + (l & 3) * 2;
                int row = rA0 + c.wr0A + (l >> 2) + h * 8;
                size_t o = (size_t)row * Hsz + col;
                atv[nf][h] = __ldcg((const float2*)(At + o));
                if (c.sA) hdv[nf][h] = __ldcg((const float2*)(g_HD + o));
            }
    }
    if (two_pending) asm volatile("cp.async.wait_group 1;" ::: "memory");
    else             asm volatile("cp.async.wait_group 0;" ::: "memory");
    __syncthreads();
    float d[2][4];
    mma_tileN2<16>(c.sb, OFF_WA, actoff, c.kA0, l, c.wr0A, c.wn0A, d);
    if (wid >= 8) {
        uint32_t ra = c.sb + OFF_RED + (uint32_t)(c.widA * 1024 + l * 32);
        uint4 v0 = {__float_as_uint(d[0][0]), __float_as_uint(d[0][1]),
                    __float_as_uint(d[0][2]), __float_as_uint(d[0][3])};
        uint4 v1 = {__float_as_uint(d[1][0]), __float_as_uint(d[1][1]),
                    __float_as_uint(d[1][2]), __float_as_uint(d[1][3])};
        sts16(ra, v0);
        sts16(ra + 16, v1);
    }
    __syncthreads();
    if (wid < 8) {
        uint32_t off = OFF_RED + (uint32_t)(c.widA * 1024 + l * 32);
        uint4 v0 = *(const uint4*)(smem + off);
        uint4 v1 = *(const uint4*)(smem + off + 16);
        d[0][0] += __uint_as_float(v0.x); d[0][1] += __uint_as_float(v0.y);
        d[0][2] += __uint_as_float(v0.z); d[0][3] += __uint_as_float(v0.w);
        d[1][0] += __uint_as_float(v1.x); d[1][1] += __uint_as_float(v1.y);
        d[1][2] += __uint_as_float(v1.z); d[1][3] += __uint_as_float(v1.w);
        #pragma unroll
        for (int nf = 0; nf < 2; nf++) {
            int col = c.jA0 + c.wn0A + nf * 8 + (l & 3) * 2;
            #pragma unroll
            for (int h = 0; h < 2; h++) {
                int row = rA0 + c.wr0A + (l >> 2) + h * 8;
                size_t o = (size_t)row * Hsz + col;
                float s0 = sigm(d[nf][h * 2]     + atv[nf][h].x);
                float s1 = sigm(d[nf][h * 2 + 1] + atv[nf][h].y);
                if (c.sA == 0) {
                    float2 zz = {s0, s1};
                    *(float2*)(g_Z + o) = zz;
                } else {
                    __half2 hp;
                    hp.x = __float2half(s0 * hdv[nf][h].x);
                    hp.y = __float2half(s1 * hdv[nf][h].y);
                    *(__half2*)(g_rh_h + o) = hp;
                }
            }
        }
    }
    arrive_g(g);
}

__device__ __forceinline__ void phaseB_exec(const Ctx& c, char* smem, uint32_t actoff,
                                            int g, int t, bool last, bool two_pending,
                                            float* __restrict__ out) {
    int rB0 = g * 32, l = c.l, wid = c.wid;
    const float* An = g_A + (size_t)2 * TBH + (size_t)t * BH;
    const float* ghn = g_gh + (size_t)(t + 1) * BH;
    int col = c.jB0 + c.wn0B + (l & 3) * 2;
    float2 anv[2], ghv[2], zv[2], hdv[2];
    if (wid < 8) {
        #pragma unroll
        for (int h = 0; h < 2; h++) {
            int row = rB0 + c.wr0B + (l >> 2) + h * 8;
            size_t o = (size_t)row * Hsz + col;
            anv[h] = __ldcg((const float2*)(An + o));
            zv[h]  = __ldcg((const float2*)(g_Z + o));
            hdv[h] = __ldcg((const float2*)(g_HD + o));
            if (!last) ghv[h] = __ldcg((const float2*)(ghn + o));
        }
    }
    if (two_pending) asm volatile("cp.async.wait_group 1;" ::: "memory");
    else             asm volatile("cp.async.wait_group 0;" ::: "memory");
    __syncthreads();
    float d[4];
    mma_tile<16>(c.sb, OFF_WB, actoff, c.kB0, l, c.wr0B, c.wn0B, d);
    if (wid >= 8) {
        uint32_t ra = c.sb + OFF_RED + (uint32_t)(c.widB * 512 + l * 16);
        uint4 v = {__float_as_uint(d[0]), __float_as_uint(d[1]),
                   __float_as_uint(d[2]), __float_as_uint(d[3])};
        sts16(ra, v);
    }
    __syncthreads();
    if (wid < 8) {
        uint32_t off = OFF_RED + (uint32_t)(c.widB * 512 + l * 16);
        uint4 v = *(const uint4*)(smem + off);
        d[0] += __uint_as_float(v.x);
        d[1] += __uint_as_float(v.y);
        d[2] += __uint_as_float(v.z);
        d[3] += __uint_as_float(v.w);
        #pragma unroll
        for (int h = 0; h < 2; h++) {
            int row = rB0 + c.wr0B + (l >> 2) + h * 8;
            size_t o = (size_t)row * Hsz + col;
            #pragma unroll
            for (int q2 = 0; q2 < 2; q2++) {
                float ht = tanhf(d[h * 2 + q2] + (q2 ? anv[h].y : anv[h].x));
                float z  = q2 ? zv[h].y : zv[h].x;
                float hd = q2 ? hdv[h].y : hdv[h].x;
                float hp = (1.f - z) * hd + z * ht;
                if (last) {
                    out[o + q2] = hp;
                } else {
                    float hdn = (q2 ? ghv[h].y : ghv[h].x) * hp;
                    g_HD[o + q2] = hdn;
                    g_hd_h[o + q2] = __float2half(hdn);
                }
            }
        }
    }
    arrive_g(g);
}

// ---------------- persistent recurrent loop kernel (pipelined phases) ---------
__global__ __launch_bounds__(512, 1) void loop_kernel(float* __restrict__ out) {
    extern __shared__ char smem[];
    uint32_t sb = smem_u32(smem);
    int tid = threadIdx.x, cta = blockIdx.x;
    int wid = tid >> 5, l = tid & 31;

    int q = cta & 15;
    int gg0 = cta >> 4;                        // serves groups gg0 and gg0+8
    Ctx c;
    c.sb = sb; c.tid = tid; c.wid = wid; c.l = l;
    c.sA  = q >> 3;
    c.jA0 = (q & 7) * 64;
    c.jB0 = q * 32;
    c.widA = wid & 7;
    c.wr0A = (c.widA & 1) * 16; c.wn0A = (c.widA >> 1) * 16;
    c.kA0  = (wid < 8) ? 0 : 256;
    c.widB = wid & 7;
    c.wr0B = (c.widB & 1) * 16; c.wn0B = (c.widB >> 1) * 8;
    c.kB0  = (wid < 8) ? 0 : 256;

    const __half* WAhi = g_Wh + (size_t)c.sA * Hsz * Hsz;
    const __half* WBhi = g_Wh + (size_t)2 * Hsz * Hsz;

    // one-time: hi weights into smem (1040B row stride)
    for (int i = tid; i < 4096; i += 512) {
        int r = i >> 6, s = i & 63;
        cpa16(sb + OFF_WA + r * 1040 + s * 16, WAhi + (size_t)(c.jA0 + r) * Hsz + s * 8);
    }
    for (int i = tid; i < 2048; i += 512) {
        int r = i >> 6, s = i & 63;
        cpa16(sb + OFF_WB + r * 1040 + s * 16, WBhi + (size_t)(c.jB0 + r) * Hsz + s * 8);
    }
    asm volatile("cp.async.commit_group;" ::: "memory");
    asm volatile("cp.async.wait_group 0;" ::: "memory");

    int grp[2] = {gg0, gg0 + 8};
    // zero-init rows of OWN groups (so per-group init arrive covers them)
    __half zh = __float2half(0.f);
    #pragma unroll
    for (int pi = 0; pi < 2; pi++) {
        int g = grp[pi];
        for (int i = tid; i < 1024; i += 512) {
            int o = (g * 32 + q * 2 + (i >> 9)) * Hsz + (i & 511);
            g_HD[o] = 0.f;
            g_hd_h[o] = zh;
        }
    }
    unsigned tg[2] = {16u, 16u};
    arrive_g(grp[0]);
    arrive_g(grp[1]);

    // pipeline prologue: wait + stage A(g0)
    wait_g(grp[0], tg[0]); tg[0] += 16;
    stage32_issue(sb + OFF_ACT0, g_hd_h, grp[0] * 32, tid);

    for (int t = 0; t < Tsz; t++) {
        bool lastT = (t == Tsz - 1);
        // ---- phase A(g0): next = A(g1) ----
        wait_g(grp[1], tg[1]); tg[1] += 16;
        stage32_issue(sb + OFF_ACT1, g_hd_h, grp[1] * 32, tid);
        phaseA_exec(c, smem, OFF_ACT0, grp[0], t, true);
        // ---- phase A(g1): next = B(g0) ----
        wait_g(grp[0], tg[0]); tg[0] += 16;
        stage32_issue(sb + OFF_ACT0, g_rh_h, grp[0] * 32, tid);
        phaseA_exec(c, smem, OFF_ACT1, grp[1], t, true);
        // ---- phase B(g0): next = B(g1) ----
        wait_g(grp[1], tg[1]); tg[1] += 16;
        stage32_issue(sb + OFF_ACT1, g_rh_h, grp[1] * 32, tid);
        phaseB_exec(c, smem, OFF_ACT0, grp[0], t, lastT, true, out);
        // ---- phase B(g1): next = A(g0) at t+1 ----
        if (!lastT) {
            wait_g(grp[0], tg[0]); tg[0] += 16;
            stage32_issue(sb + OFF_ACT0, g_hd_h, grp[0] * 32, tid);
        }
        phaseB_exec(c, smem, OFF_ACT1, grp[1], t, lastT, !lastT, out);
    }
}

// ---------------- launch ----------------
extern "C" void kernel_launch(void* const* d_in, const int* in_sizes, int n_in,
                              void* d_out, int out_size) {
    const float* x    = (const float*)d_in[0];
    const float* xl   = (const float*)d_in[1];
    const float* mk   = (const float*)d_in[2];
    const float* dl   = (const float*)d_in[3];
    const float* xm   = (const float*)d_in[4];
    const float* Wz   = (const float*)d_in[5];
    const float* bz   = (const float*)d_in[6];
    const float* Wr   = (const float*)d_in[7];
    const float* br   = (const float*)d_in[8];
    const float* Wn   = (const float*)d_in[9];
    const float* bn   = (const float*)d_in[10];
    const float* Wgx  = (const float*)d_in[11];
    const float* bgx  = (const float*)d_in[12];
    const float* Wgh  = (const float*)d_in[13];
    const float* bgh  = (const float*)d_in[14];

    static int smem_set = 0;
    if (!smem_set) {
        cudaFuncSetAttribute(loop_kernel,
                             cudaFuncAttributeMaxDynamicSharedMemorySize, SMEM_TOTAL);
        cudaFuncSetAttribute(p12_kernel,
                             cudaFuncAttributeMaxDynamicSharedMemorySize, PG_SMEM);
        smem_set = 1;
    }

    p0prep_kernel<<<65536 + 4864 + 1, 256>>>(x, xl, mk, dl, xm, Wgx, bgx,
                                             Wz, Wr, Wn, Wgh);
    p12_kernel<<<dim3(16, 1024), 256, PG_SMEM>>>(bz, br, bn, bgh);
    dummy_kernel<<<1, 32>>>();
    loop_kernel<<<NCTA, 512, SMEM_TOTAL>>>((float*)d_out);
}

// round 15
// speedup vs baseline: 1.0860x; 1.0860x over previous
#include <cuda_runtime.h>
#include <cuda_fp16.h>
#include <cstdint>

#define Bsz 512
#define Tsz 256
#define Dsz 128
#define Hsz 512
#define GIN 768
#define TB  (Tsz*Bsz)          /* 131072 */
#define BH  (Bsz*Hsz)          /* 262144 */
#define NCTA 128

static const size_t TBH = (size_t)TB * Hsz;   /* 67108864 */

// loop-kernel smem (bytes): WA 64x1040, WB 32x1040, ACT 32x1040, RED 8KB
#define OFF_WA  0u
#define OFF_WB  66560u
#define OFF_ACT 99840u
#define OFF_RED 133120u
#define SMEM_TOTAL 141312

// precompute-gemm smem: 2 bufs x 2 tiles x (128 rows x 144B)
#define PG_TILE 18432u
#define PG_BUF  36864u
#define PG_SMEM 73728

// ---------------- scratch (__device__ globals: allocation-free) ----------------
__device__ __half g_A[201326592];       // 3 x (T*B, H): affine terms, fp16
__device__ float g_gh[67108864];        // (T*B, H): hidden decay gamma_h (fp32)
__device__ float g_HD[BH];              // hd = gh*h (fp32)
__device__ float g_Z [BH];              // z gate
__device__ __half g_x1h[TB*256];        // [xt|m] fp16
__device__ __half g_dh [TB*128];        // delta fp16
__device__ __half g_hd_h[BH];           // hd fp16
__device__ __half g_rh_h[BH];           // r*hd fp16
__device__ __half g_Wh[3*Hsz*Hsz];      // hidden slices (hi only)
__device__ __half g_W1hh[3*Hsz*256];    // x|m slices (hi only)
__device__ __half g_Wghh[Hsz*128];      // Wgh (hi only)
__device__ unsigned g_bar[512];         // 16 group counters, 128B apart

// ---------------- small helpers ----------------
__device__ __forceinline__ float sigm(float x) { return 1.f / (1.f + expf(-x)); }
__device__ __forceinline__ uint32_t smem_u32(const void* p) {
    uint32_t a;
    asm("{ .reg .u64 t; cvta.to.shared.u64 t, %1; cvt.u32.u64 %0, t; }" : "=r"(a) : "l"(p));
    return a;
}
__device__ __forceinline__ void cpa16(uint32_t dst, const void* src) {
    asm volatile("cp.async.cg.shared.global [%0],[%1],16;" :: "r"(dst), "l"(src));
}
__device__ __forceinline__ void sts16(uint32_t a, uint4 v) {
    asm volatile("st.shared.v4.b32 [%0],{%1,%2,%3,%4};"
                 :: "r"(a), "r"(v.x), "r"(v.y), "r"(v.z), "r"(v.w));
}
__device__ __forceinline__ void ldsm4(uint32_t &r0, uint32_t &r1, uint32_t &r2,
                                      uint32_t &r3, uint32_t addr) {
    asm volatile("ldmatrix.sync.aligned.m8n8.x4.shared.b16 {%0,%1,%2,%3},[%4];"
                 : "=r"(r0), "=r"(r1), "=r"(r2), "=r"(r3) : "r"(addr));
}
__device__ __forceinline__ void mma_f16(float* d, const uint32_t* a,
                                        uint32_t b0, uint32_t b1) {
    asm volatile("mma.sync.aligned.m16n8k16.row.col.f32.f16.f16.f32 "
                 "{%0,%1,%2,%3},{%4,%5,%6,%7},{%8,%9},{%0,%1,%2,%3};"
                 : "+f"(d[0]), "+f"(d[1]), "+f"(d[2]), "+f"(d[3])
                 : "r"(a[0]), "r"(a[1]), "r"(a[2]), "r"(a[3]), "r"(b0), "r"(b1));
}
__device__ __forceinline__ float2 ldA2(const __half* p) {
    unsigned u = __ldcg((const unsigned*)p);
    __half2 h = *(__half2*)&u;
    return __half22float2(h);
}

// ---------------- group barrier primitives (16 CTAs per group) ----------------
__device__ __forceinline__ void arrive_g(int g) {
    __syncthreads();
    if (threadIdx.x == 0) {
        asm volatile("red.release.gpu.global.add.u32 [%0],%1;"
                     :: "l"(g_bar + g * 32), "r"(1u) : "memory");
    }
}
__device__ __forceinline__ void wait_g(int g, unsigned target) {
    if (threadIdx.x == 0) {
        unsigned v;
        do {
            asm volatile("ld.acquire.gpu.global.u32 %0,[%1];"
                         : "=r"(v) : "l"(g_bar + g * 32) : "memory");
        } while (v < target);
    }
    __syncthreads();
}

// ---------------- K0: fused p0 (input decay staging) + weight split + bar -----
__global__ void p0prep_kernel(const float* __restrict__ x,  const float* __restrict__ xl,
                              const float* __restrict__ mk, const float* __restrict__ dl,
                              const float* __restrict__ xmean,
                              const float* __restrict__ Wgx, const float* __restrict__ bgx,
                              const float* __restrict__ Wz, const float* __restrict__ Wr,
                              const float* __restrict__ Wn, const float* __restrict__ Wgh) {
    int bx = blockIdx.x;
    if (bx < 8192) {
        #pragma unroll
        for (int u = 0; u < 8; u++) {
            int idx = bx * 2048 + u * 256 + threadIdx.x;
            int d   = idx & 127;
            int row = idx >> 7;
            int t   = row >> 9;
            int b   = row & 511;
            size_t xi = ((size_t)b * Tsz + t) * Dsz + d;
            float dv = dl[xi], mv = mk[xi];
            float gx = expf(-fmaxf(0.f, dv * Wgx[d * Dsz + d] + bgx[d]));
            float xt = mv * x[xi] + (1.f - mv) * (gx * xl[xi] + (1.f - gx) * xmean[d]);
            g_x1h[(size_t)row * 256 + d]       = __float2half(xt);
            g_x1h[(size_t)row * 256 + 128 + d] = __float2half(mv);
            g_dh [(size_t)row * 128 + d]       = __float2half(dv);
        }
    } else if (bx < 8192 + 608) {
        #pragma unroll
        for (int u = 0; u < 8; u++) {
            int idx = (bx - 8192) * 2048 + u * 256 + threadIdx.x;
            if (idx < 786432) {                 // hidden slices (hi only)
                int k = idx & 511, j = (idx >> 9) & 511, g = idx >> 18;
                const float* W = (g == 0) ? Wz : (g == 1) ? Wr : Wn;
                g_Wh[idx] = __float2half(W[(size_t)j * GIN + 128 + k]);
            } else if (idx < 786432 + 393216) { // x|m slices (hi only)
                int e = idx - 786432;
                int k = e & 255, j = (e >> 8) & 511, g = e >> 17;
                const float* W = (g == 0) ? Wz : (g == 1) ? Wr : Wn;
                int col = (k < 128) ? k : (512 + k);
                g_W1hh[e] = __float2half(W[(size_t)j * GIN + col]);
            } else if (idx < 786432 + 393216 + 65536) {
                int e = idx - 786432 - 393216;
                g_Wghh[e] = __float2half(Wgh[e]);
            }
        }
    } else {
        g_bar[threadIdx.x] = 0u;
        g_bar[threadIdx.x + 256] = 0u;
    }
}

// ---------------- precompute GEMM core (fp16 single-term) ---------------------
template<int KCH>
__device__ __forceinline__ void pg_core(uint32_t sb,
        const __half* __restrict__ Ah, const __half* __restrict__ Bh,
        int row0, int j0, int K, int tid, float d[2][8][4]) {
    #pragma unroll
    for (int mt = 0; mt < 2; mt++)
        #pragma unroll
        for (int nf = 0; nf < 8; nf++)
            #pragma unroll
            for (int i = 0; i < 4; i++) d[mt][nf][i] = 0.f;

    int wid = tid >> 5, l = tid & 31;
    int wr0 = (wid >> 1) * 32;
    int wn0 = (wid & 1) * 64;
    uint32_t aoff = (uint32_t)((wr0 + (l & 15)) * 144 + ((l >> 4) * 8) * 2);
    uint32_t boff = (uint32_t)((wn0 + ((l >> 4) << 3) + (l & 7)) * 144
                               + (((l >> 3) & 1) * 8) * 2);
    int sr = tid >> 3, ss = tid & 7;

    #pragma unroll
    for (int u = 0; u < 4; u++) {
        int r = sr + u * 32;
        uint32_t db = sb + (uint32_t)(r * 144 + ss * 16);
        cpa16(db,           Ah + (size_t)(row0 + r) * K + ss * 8);
        cpa16(db + PG_TILE, Bh + (size_t)(j0 + r) * K + ss * 8);
    }
    asm volatile("cp.async.commit_group;" ::: "memory");

    for (int c = 0; c < KCH; c++) {
        if (c + 1 < KCH) {
            uint32_t bb = sb + ((c + 1) & 1) * PG_BUF;
            #pragma unroll
            for (int u = 0; u < 4; u++) {
                int r = sr + u * 32;
                uint32_t db = bb + (uint32_t)(r * 144 + ss * 16);
                int ko = (c + 1) * 64 + ss * 8;
                cpa16(db,           Ah + (size_t)(row0 + r) * K + ko);
                cpa16(db + PG_TILE, Bh + (size_t)(j0 + r) * K + ko);
            }
            asm volatile("cp.async.commit_group;" ::: "memory");
            asm volatile("cp.async.wait_group 1;" ::: "memory");
        } else {
            asm volatile("cp.async.wait_group 0;" ::: "memory");
        }
        __syncthreads();
        uint32_t bb = sb + (c & 1) * PG_BUF;
        #pragma unroll
        for (int ks = 0; ks < 4; ks++) {
            uint32_t ko = (uint32_t)(ks * 32);
            uint32_t ah[2][4], bh[4][4];
            #pragma unroll
            for (int mt = 0; mt < 2; mt++) {
                uint32_t a = bb + aoff + (uint32_t)(mt * 16 * 144) + ko;
                ldsm4(ah[mt][0], ah[mt][1], ah[mt][2], ah[mt][3], a);
            }
            #pragma unroll
            for (int p = 0; p < 4; p++) {
                uint32_t b = bb + PG_TILE + boff + (uint32_t)(p * 16 * 144) + ko;
                ldsm4(bh[p][0], bh[p][1], bh[p][2], bh[p][3], b);
            }
            #pragma unroll
            for (int p = 0; p < 4; p++)
                #pragma unroll
                for (int mt = 0; mt < 2; mt++) {
                    mma_f16(d[mt][2*p],   ah[mt], bh[p][0], bh[p][1]);
                    mma_f16(d[mt][2*p+1], ah[mt], bh[p][2], bh[p][3]);
                }
        }
        __syncthreads();
    }
}

// ---------------- K1: fused p1m + p2m -----------------------------------------
__global__ __launch_bounds__(256, 2) void p12_kernel(
        const float* __restrict__ bz, const float* __restrict__ br,
        const float* __restrict__ bn, const float* __restrict__ bgh) {
    extern __shared__ char smem[];
    uint32_t sb = smem_u32(smem);
    int tid = threadIdx.x;
    int row0 = blockIdx.y * 128;
    int wid = tid >> 5, l = tid & 31;
    int wr0 = (wid >> 1) * 32, wn0 = (wid & 1) * 64;
    float d[2][8][4];
    if (blockIdx.x < 12) {
        int s = blockIdx.x >> 2;
        int j0 = (blockIdx.x & 3) * 128;
        const float* bias = (s == 0) ? bz : (s == 1) ? br : bn;
        __half* out = g_A + (size_t)s * TBH;
        pg_core<4>(sb, g_x1h, g_W1hh + (size_t)s * Hsz * 256, row0, j0, 256, tid, d);
        #pragma unroll
        for (int mt = 0; mt < 2; mt++)
            #pragma unroll
            for (int nf = 0; nf < 8; nf++)
                #pragma unroll
                for (int h = 0; h < 2; h++) {
                    int row = row0 + wr0 + mt * 16 + (l >> 2) + h * 8;
                    int col = j0 + wn0 + nf * 8 + (l & 3) * 2;
                    __half2 v;
                    v.x = __float2half(d[mt][nf][h * 2]     + bias[col]);
                    v.y = __float2half(d[mt][nf][h * 2 + 1] + bias[col + 1]);
                    *(__half2*)(out + (size_t)row * Hsz + col) = v;
                }
    } else {
        int j0 = (blockIdx.x - 12) * 128;
        pg_core<2>(sb, g_dh, g_Wghh, row0, j0, 128, tid, d);
        #pragma unroll
        for (int mt = 0; mt < 2; mt++)
            #pragma unroll
            for (int nf = 0; nf < 8; nf++)
                #pragma unroll
                for (int h = 0; h < 2; h++) {
                    int row = row0 + wr0 + mt * 16 + (l >> 2) + h * 8;
                    int col = j0 + wn0 + nf * 8 + (l & 3) * 2;
                    float2 v;
                    v.x = expf(-fmaxf(0.f, d[mt][nf][h * 2]     + bgh[col]));
                    v.y = expf(-fmaxf(0.f, d[mt][nf][h * 2 + 1] + bgh[col + 1]));
                    *(float2*)(g_gh + (size_t)row * Hsz + col) = v;
                }
    }
}

__global__ void dummy_kernel() {}

// ---------------- loop helpers ------------------------------------------------
// issue cp.async staging of a 32x512 fp16 act tile (stride 1040); caller waits
__device__ __forceinline__ void stage32_issue(uint32_t A, const __half* __restrict__ gact,
                                              int r0, int tid) {
    #pragma unroll
    for (int u = 0; u < 4; u++) {
        int i = u * 512 + tid;
        cpa16(A + (uint32_t)((i >> 6) * 1040 + (i & 63) * 16),
              gact + (size_t)(r0 + (i >> 6)) * Hsz + (i & 63) * 8);
    }
    asm volatile("cp.async.commit_group;" ::: "memory");
}
__device__ __forceinline__ void stage_wait() {
    asm volatile("cp.async.wait_group 0;" ::: "memory");
    __syncthreads();
}

// 16x16 warp-tile fp16 GEMM over k range [k0, k0+KS*16); 8 accumulator chains
template<int KS>
__device__ __forceinline__ void mma_tileN2(uint32_t sb, uint32_t woff, int k0,
                                           int l, int wr0, int wn0, float d[2][4]) {
    uint32_t Ab = sb + OFF_ACT;
    uint32_t aoff = (uint32_t)((wr0 + (l & 15)) * 1040 + ((l >> 4) * 8) * 2 + k0 * 2);
    uint32_t b1o  = (uint32_t)((wn0 + (l & 7)) * 1040 + (l >> 3) * 16 + k0 * 2);
    uint32_t b2o  = b1o + 8 * 1040;
    float c[8][4];
    #pragma unroll
    for (int i = 0; i < 8; i++)
        #pragma unroll
        for (int j = 0; j < 4; j++) c[i][j] = 0.f;
    #pragma unroll
    for (int it = 0; it < KS / 2; it++) {
        uint32_t a0[4], a1[4], b1[4], b2[4];
        ldsm4(a0[0], a0[1], a0[2], a0[3], Ab + aoff + it * 64);
        ldsm4(a1[0], a1[1], a1[2], a1[3], Ab + aoff + it * 64 + 32);
        ldsm4(b1[0], b1[1], b1[2], b1[3], sb + woff + b1o + it * 64);
        ldsm4(b2[0], b2[1], b2[2], b2[3], sb + woff + b2o + it * 64);
        int p = (it & 1) * 4;
        mma_f16(c[p + 0], a0, b1[0], b1[1]);
        mma_f16(c[p + 1], a0, b2[0], b2[1]);
        mma_f16(c[p + 2], a1, b1[2], b1[3]);
        mma_f16(c[p + 3], a1, b2[2], b2[3]);
    }
    #pragma unroll
    for (int i = 0; i < 4; i++) {
        d[0][i] = (c[0][i] + c[2][i]) + (c[4][i] + c[6][i]);
        d[1][i] = (c[1][i] + c[3][i]) + (c[5][i] + c[7][i]);
    }
}

// 16x8 warp-tile fp16 GEMM (phase B), 4 accumulator chains
template<int KS>
__device__ __forceinline__ void mma_tile(uint32_t sb, uint32_t woff, int k0,
                                         int l, int wr0, int wn0, float d[4]) {
    uint32_t Ab = sb + OFF_ACT;
    uint32_t aoff = (uint32_t)((wr0 + (l & 15)) * 1040 + ((l >> 4) * 8) * 2 + k0 * 2);
    uint32_t boff = (uint32_t)((wn0 + (l & 7)) * 1040 + (l >> 3) * 16 + k0 * 2);
    float c0[4] = {0,0,0,0}, c1[4] = {0,0,0,0};
    float c2[4] = {0,0,0,0}, c3[4] = {0,0,0,0};
    #pragma unroll
    for (int it = 0; it < KS / 2; it++) {
        uint32_t a0[4], a1[4], b[4];
        ldsm4(a0[0], a0[1], a0[2], a0[3], Ab + aoff + it * 64);
        ldsm4(a1[0], a1[1], a1[2], a1[3], Ab + aoff + it * 64 + 32);
        ldsm4(b[0], b[1], b[2], b[3], sb + woff + boff + it * 64);
        if (it & 1) {
            mma_f16(c2, a0, b[0], b[1]);
            mma_f16(c3, a1, b[2], b[3]);
        } else {
            mma_f16(c0, a0, b[0], b[1]);
            mma_f16(c1, a1, b[2], b[3]);
        }
    }
    #pragma unroll
    for (int i = 0; i < 4; i++) d[i] = (c0[i] + c1[i]) + (c2[i] + c3[i]);
}

// ---------------- persistent recurrent loop kernel (512 thr, 2-group ilv) -----
__global__ __launch_bounds__(512, 1) void loop_kernel(float* __restrict__ out) {
    extern __shared__ char smem[];
    uint32_t sb = smem_u32(smem);
    int tid = threadIdx.x, cta = blockIdx.x;
    int wid = tid >> 5, l = tid & 31;

    int q = cta & 15;
    int gg0 = cta >> 4;                        // serves groups gg0 and gg0+8
    int sA  = q >> 3;                          // 0 = z, 1 = r
    int jA0 = (q & 7) * 64;
    int jB0 = q * 32;
    const __half* WAhi = g_Wh + (size_t)sA * Hsz * Hsz;
    const __half* WBhi = g_Wh + (size_t)2 * Hsz * Hsz;

    // one-time: hi weights into smem (1040B row stride)
    for (int i = tid; i < 4096; i += 512) {
        int r = i >> 6, s = i & 63;
        cpa16(sb + OFF_WA + r * 1040 + s * 16, WAhi + (size_t)(jA0 + r) * Hsz + s * 8);
    }
    for (int i = tid; i < 2048; i += 512) {
        int r = i >> 6, s = i & 63;
        cpa16(sb + OFF_WB + r * 1040 + s * 16, WBhi + (size_t)(jB0 + r) * Hsz + s * 8);
    }
    asm volatile("cp.async.commit_group;" ::: "memory");
    asm volatile("cp.async.wait_group 0;" ::: "memory");

    __half zh = __float2half(0.f);
    for (int i = tid; i < 2048; i += 512) {
        int o = cta * 2048 + i;
        g_HD[o] = 0.f;
        g_hd_h[o] = zh;
    }
    int grp[2] = {gg0, gg0 + 8};
    unsigned tg[2] = {16u, 16u};
    arrive_g(grp[0]);
    arrive_g(grp[1]);

    // phase A: 8 slots of 16x16 over 32x64, 2-way K-split (warps 8-15: k>=256)
    int widA = wid & 7;
    int wr0A = (widA & 1) * 16, wn0A = (widA >> 1) * 16;
    int kA0  = (wid < 8) ? 0 : 256;
    // phase B: 8 slots of 16x8 over 32x32, 2-way K-split
    int widB = wid & 7;
    int wr0B = (widB & 1) * 16, wn0B = (widB >> 1) * 8;
    int kB0  = (wid < 8) ? 0 : 256;

    for (int t = 0; t < Tsz; t++) {
        // ================== phase A for both groups ==========================
        #pragma unroll 1
        for (int pi = 0; pi < 2; pi++) {
            int g = grp[pi];
            wait_g(g, tg[pi]); tg[pi] += 16;
            int rA0 = g * 32;
            stage32_issue(sb + OFF_ACT, g_hd_h, rA0, tid);
            const __half* At = g_A + (size_t)sA * TBH + (size_t)t * BH;
            float2 atv[2][2], hdv[2][2];
            if (wid < 8) {
                #pragma unroll
                for (int nf = 0; nf < 2; nf++)
                    #pragma unroll
                    for (int h = 0; h < 2; h++) {
                        int col = jA0 + wn0A + nf * 8 + (l & 3) * 2;
                        int row = rA0 + wr0A + (l >> 2) + h * 8;
                        size_t o = (size_t)row * Hsz + col;
                        atv[nf][h] = ldA2(At + o);
                        if (sA) hdv[nf][h] = __ldcg((const float2*)(g_HD + o));
                    }
            }
            stage_wait();
            float d[2][4];
            mma_tileN2<16>(sb, OFF_WA, kA0, l, wr0A, wn0A, d);
            if (wid >= 8) {
                uint32_t ra = sb + OFF_RED + (uint32_t)(widA * 1024 + l * 32);
                uint4 v0 = {__float_as_uint(d[0][0]), __float_as_uint(d[0][1]),
                            __float_as_uint(d[0][2]), __float_as_uint(d[0][3])};
                uint4 v1 = {__float_as_uint(d[1][0]), __float_as_uint(d[1][1]),
                            __float_as_uint(d[1][2]), __float_as_uint(d[1][3])};
                sts16(ra, v0);
                sts16(ra + 16, v1);
            }
            __syncthreads();
            if (wid < 8) {
                uint32_t ra = sb + OFF_RED + (uint32_t)(widA * 1024 + l * 32);
                uint4 v0 = *(const uint4*)(smem + (ra - sb));
                uint4 v1 = *(const uint4*)(smem + (ra - sb) + 16);
                d[0][0] += __uint_as_float(v0.x); d[0][1] += __uint_as_float(v0.y);
                d[0][2] += __uint_as_float(v0.z); d[0][3] += __uint_as_float(v0.w);
                d[1][0] += __uint_as_float(v1.x); d[1][1] += __uint_as_float(v1.y);
                d[1][2] += __uint_as_float(v1.z); d[1][3] += __uint_as_float(v1.w);
                #pragma unroll
                for (int nf = 0; nf < 2; nf++) {
                    int col = jA0 + wn0A + nf * 8 + (l & 3) * 2;
                    #pragma unroll
                    for (int h = 0; h < 2; h++) {
                        int row = rA0 + wr0A + (l >> 2) + h * 8;
                        size_t o = (size_t)row * Hsz + col;
                        float s0 = sigm(d[nf][h * 2]     + atv[nf][h].x);
                        float s1 = sigm(d[nf][h * 2 + 1] + atv[nf][h].y);
                        if (sA == 0) {
                            float2 zz = {s0, s1};
                            *(float2*)(g_Z + o) = zz;
                        } else {
                            __half2 hp;
                            hp.x = __float2half(s0 * hdv[nf][h].x);
                            hp.y = __float2half(s1 * hdv[nf][h].y);
                            *(__half2*)(g_rh_h + o) = hp;
                        }
                    }
                }
            }
            arrive_g(g);
        }

        // ================== phase B for both groups ==========================
        #pragma unroll 1
        for (int pi = 0; pi < 2; pi++) {
            int g = grp[pi];
            wait_g(g, tg[pi]); tg[pi] += 16;
            int rB0 = g * 32;
            stage32_issue(sb + OFF_ACT, g_rh_h, rB0, tid);
            const __half* An = g_A + (size_t)2 * TBH + (size_t)t * BH;
            const float* ghn = g_gh + (size_t)(t + 1) * BH;
            bool last = (t == Tsz - 1);
            int col = jB0 + wn0B + (l & 3) * 2;
            float2 anv[2], ghv[2], zv[2], hdv[2];
            if (wid < 8) {
                #pragma unroll
                for (int h = 0; h < 2; h++) {
                    int row = rB0 + wr0B + (l >> 2) + h * 8;
                    size_t o = (size_t)row * Hsz + col;
                    anv[h] = ldA2(An + o);
                    zv[h]  = __ldcg((const float2*)(g_Z + o));
                    hdv[h] = __ldcg((const float2*)(g_HD + o));
                    if (!last) ghv[h] = __ldcg((const float2*)(ghn + o));
                }
            }
            stage_wait();
            float d[4];
            mma_tile<16>(sb, OFF_WB, kB0, l, wr0B, wn0B, d);
            if (wid >= 8) {
                uint32_t ra = sb + OFF_RED + (uint32_t)(widB * 512 + l * 16);
                uint4 v = {__float_as_uint(d[0]), __float_as_uint(d[1]),
                           __float_as_uint(d[2]), __float_as_uint(d[3])};
                sts16(ra, v);
            }
            __syncthreads();
            if (wid < 8) {
                uint32_t ra = sb + OFF_RED + (uint32_t)(widB * 512 + l * 16);
                uint4 v = *(const uint4*)(smem + (ra - sb));
                d[0] += __uint_as_float(v.x);
                d[1] += __uint_as_float(v.y);
                d[2] += __uint_as_float(v.z);
                d[3] += __uint_as_float(v.w);
                #pragma unroll
                for (int h = 0; h < 2; h++) {
                    int row = rB0 + wr0B + (l >> 2) + h * 8;
                    size_t o = (size_t)row * Hsz + col;
                    #pragma unroll
                    for (int q2 = 0; q2 < 2; q2++) {
                        float ht = tanhf(d[h * 2 + q2] + (q2 ? anv[h].y : anv[h].x));
                        float z  = q2 ? zv[h].y : zv[h].x;
                        float hd = q2 ? hdv[h].y : hdv[h].x;
                        float hp = (1.f - z) * hd + z * ht;
                        if (last) {
                            out[o + q2] = hp;
                        } else {
                            float hdn = (q2 ? ghv[h].y : ghv[h].x) * hp;
                            g_HD[o + q2] = hdn;
                            g_hd_h[o + q2] = __float2half(hdn);
                        }
                    }
                }
            }
            arrive_g(g);
        }
    }
}

// ---------------- launch ----------------
extern "C" void kernel_launch(void* const* d_in, const int* in_sizes, int n_in,
                              void* d_out, int out_size) {
    const float* x    = (const float*)d_in[0];
    const float* xl   = (const float*)d_in[1];
    const float* mk   = (const float*)d_in[2];
    const float* dl   = (const float*)d_in[3];
    const float* xm   = (const float*)d_in[4];
    const float* Wz   = (const float*)d_in[5];
    const float* bz   = (const float*)d_in[6];
    const float* Wr   = (const float*)d_in[7];
    const float* br   = (const float*)d_in[8];
    const float* Wn   = (const float*)d_in[9];
    const float* bn   = (const float*)d_in[10];
    const float* Wgx  = (const float*)d_in[11];
    const float* bgx  = (const float*)d_in[12];
    const float* Wgh  = (const float*)d_in[13];
    const float* bgh  = (const float*)d_in[14];

    static int smem_set = 0;
    if (!smem_set) {
        cudaFuncSetAttribute(loop_kernel,
                             cudaFuncAttributeMaxDynamicSharedMemorySize, SMEM_TOTAL);
        cudaFuncSetAttribute(p12_kernel,
                             cudaFuncAttributeMaxDynamicSharedMemorySize, PG_SMEM);
        smem_set = 1;
    }

    p0prep_kernel<<<8192 + 608 + 1, 256>>>(x, xl, mk, dl, xm, Wgx, bgx,
                                           Wz, Wr, Wn, Wgh);
    p12_kernel<<<dim3(16, 1024), 256, PG_SMEM>>>(bz, br, bn, bgh);
    dummy_kernel<<<1, 32>>>();
    loop_kernel<<<NCTA, 512, SMEM_TOTAL>>>((float*)d_out);
}

// round 16
// speedup vs baseline: 1.1641x; 1.0719x over previous
#include <cuda_runtime.h>
#include <cuda_fp16.h>
#include <cstdint>

#define Bsz 512
#define Tsz 256
#define Dsz 128
#define Hsz 512
#define GIN 768
#define TB  (Tsz*Bsz)          /* 131072 */
#define BH  (Bsz*Hsz)          /* 262144 */
#define NCTA 128

static const size_t TBH = (size_t)TB * Hsz;   /* 67108864 */

// loop-kernel smem (bytes): WA 64x1040, WB 32x1040, ACT 32x1040, RED 8KB
#define OFF_WA  0u
#define OFF_WB  66560u
#define OFF_ACT 99840u
#define OFF_RED 133120u
#define SMEM_TOTAL 141312

// precompute-gemm smem: 2 bufs x 2 tiles x (128 rows x 144B)
#define PG_TILE 18432u
#define PG_BUF  36864u
#define PG_SMEM 73728

// ---------------- scratch (__device__ globals: allocation-free) ----------------
__device__ float g_A [201326592];       // 3 x (T*B, H): affine terms (bias incl.)
__device__ float g_gh[67108864];        // (T*B, H): hidden decay gamma_h
__device__ float g_HD[BH];              // hd = gh*h (fp32)
__device__ float g_Z [BH];              // z gate
__device__ __half g_x1h[TB*256];        // [xt|m] fp16
__device__ __half g_dh [TB*128];        // delta fp16
__device__ __half g_hd_h[BH];           // hd fp16
__device__ __half g_rh_h[BH];           // r*hd fp16
__device__ __half g_Wh[3*Hsz*Hsz];      // hidden slices (hi only)
__device__ __half g_W1hh[3*Hsz*256];    // x|m slices (hi only)
__device__ __half g_Wghh[Hsz*128];      // Wgh (hi only)
__device__ unsigned g_bar[512];         // 16 group counters, 128B apart

// ---------------- small helpers ----------------
__device__ __forceinline__ float sigm(float x) { return 1.f / (1.f + expf(-x)); }
__device__ __forceinline__ uint32_t smem_u32(const void* p) {
    uint32_t a;
    asm("{ .reg .u64 t; cvta.to.shared.u64 t, %1; cvt.u32.u64 %0, t; }" : "=r"(a) : "l"(p));
    return a;
}
__device__ __forceinline__ void cpa16(uint32_t dst, const void* src) {
    asm volatile("cp.async.cg.shared.global [%0],[%1],16;" :: "r"(dst), "l"(src));
}
__device__ __forceinline__ void sts16(uint32_t a, uint4 v) {
    asm volatile("st.shared.v4.b32 [%0],{%1,%2,%3,%4};"
                 :: "r"(a), "r"(v.x), "r"(v.y), "r"(v.z), "r"(v.w));
}
__device__ __forceinline__ void ldsm4(uint32_t &r0, uint32_t &r1, uint32_t &r2,
                                      uint32_t &r3, uint32_t addr) {
    asm volatile("ldmatrix.sync.aligned.m8n8.x4.shared.b16 {%0,%1,%2,%3},[%4];"
                 : "=r"(r0), "=r"(r1), "=r"(r2), "=r"(r3) : "r"(addr));
}
__device__ __forceinline__ void mma_f16(float* d, const uint32_t* a,
                                        uint32_t b0, uint32_t b1) {
    asm volatile("mma.sync.aligned.m16n8k16.row.col.f32.f16.f16.f32 "
                 "{%0,%1,%2,%3},{%4,%5,%6,%7},{%8,%9},{%0,%1,%2,%3};"
                 : "+f"(d[0]), "+f"(d[1]), "+f"(d[2]), "+f"(d[3])
                 : "r"(a[0]), "r"(a[1]), "r"(a[2]), "r"(a[3]), "r"(b0), "r"(b1));
}

// ---------------- group barrier primitives (16 CTAs per group) ----------------
__device__ __forceinline__ void arrive_g(int g) {
    __syncthreads();
    if (threadIdx.x == 0) {
        asm volatile("red.release.gpu.global.add.u32 [%0],%1;"
                     :: "l"(g_bar + g * 32), "r"(1u) : "memory");
    }
}
__device__ __forceinline__ void wait_g(int g, unsigned target) {
    if (threadIdx.x == 0) {
        unsigned v;
        do {
            asm volatile("ld.acquire.gpu.global.u32 %0,[%1];"
                         : "=r"(v) : "l"(g_bar + g * 32) : "memory");
        } while (v < target);
    }
    __syncthreads();
}

// ---------------- K0: fused p0 (input decay staging) + weight split + bar -----
__global__ void p0prep_kernel(const float* __restrict__ x,  const float* __restrict__ xl,
                              const float* __restrict__ mk, const float* __restrict__ dl,
                              const float* __restrict__ xmean,
                              const float* __restrict__ Wgx, const float* __restrict__ bgx,
                              const float* __restrict__ Wz, const float* __restrict__ Wr,
                              const float* __restrict__ Wn, const float* __restrict__ Wgh) {
    int bx = blockIdx.x;
    if (bx < 65536) {
        int idx = bx * 256 + threadIdx.x;
        int d   = idx & 127;
        int row = idx >> 7;
        int t   = row >> 9;
        int b   = row & 511;
        size_t xi = ((size_t)b * Tsz + t) * Dsz + d;
        float dv = dl[xi], mv = mk[xi];
        float gx = expf(-fmaxf(0.f, dv * Wgx[d * Dsz + d] + bgx[d]));
        float xt = mv * x[xi] + (1.f - mv) * (gx * xl[xi] + (1.f - gx) * xmean[d]);
        g_x1h[(size_t)row * 256 + d]       = __float2half(xt);
        g_x1h[(size_t)row * 256 + 128 + d] = __float2half(mv);
        g_dh [(size_t)row * 128 + d]       = __float2half(dv);
    } else if (bx < 65536 + 4864) {
        int idx = (bx - 65536) * 256 + threadIdx.x;
        if (idx < 786432) {                 // hidden slices (hi only)
            int k = idx & 511, j = (idx >> 9) & 511, g = idx >> 18;
            const float* W = (g == 0) ? Wz : (g == 1) ? Wr : Wn;
            g_Wh[idx] = __float2half(W[(size_t)j * GIN + 128 + k]);
        } else if (idx < 786432 + 393216) { // x|m slices (hi only)
            int e = idx - 786432;
            int k = e & 255, j = (e >> 8) & 511, g = e >> 17;
            const float* W = (g == 0) ? Wz : (g == 1) ? Wr : Wn;
            int col = (k < 128) ? k : (512 + k);
            g_W1hh[e] = __float2half(W[(size_t)j * GIN + col]);
        } else if (idx < 786432 + 393216 + 65536) {
            int e = idx - 786432 - 393216;
            g_Wghh[e] = __float2half(Wgh[e]);
        }
    } else {
        g_bar[threadIdx.x] = 0u;
        g_bar[threadIdx.x + 256] = 0u;
    }
}

// ---------------- precompute GEMM core (fp16 single-term) ---------------------
template<int KCH>
__device__ __forceinline__ void pg_core(uint32_t sb,
        const __half* __restrict__ Ah, const __half* __restrict__ Bh,
        int row0, int j0, int K, int tid, float d[2][8][4]) {
    #pragma unroll
    for (int mt = 0; mt < 2; mt++)
        #pragma unroll
        for (int nf = 0; nf < 8; nf++)
            #pragma unroll
            for (int i = 0; i < 4; i++) d[mt][nf][i] = 0.f;

    int wid = tid >> 5, l = tid & 31;
    int wr0 = (wid >> 1) * 32;
    int wn0 = (wid & 1) * 64;
    uint32_t aoff = (uint32_t)((wr0 + (l & 15)) * 144 + ((l >> 4) * 8) * 2);
    uint32_t boff = (uint32_t)((wn0 + ((l >> 4) << 3) + (l & 7)) * 144
                               + (((l >> 3) & 1) * 8) * 2);
    int sr = tid >> 3, ss = tid & 7;

    #pragma unroll
    for (int u = 0; u < 4; u++) {
        int r = sr + u * 32;
        uint32_t db = sb + (uint32_t)(r * 144 + ss * 16);
        cpa16(db,           Ah + (size_t)(row0 + r) * K + ss * 8);
        cpa16(db + PG_TILE, Bh + (size_t)(j0 + r) * K + ss * 8);
    }
    asm volatile("cp.async.commit_group;" ::: "memory");

    for (int c = 0; c < KCH; c++) {
        if (c + 1 < KCH) {
            uint32_t bb = sb + ((c + 1) & 1) * PG_BUF;
            #pragma unroll
            for (int u = 0; u < 4; u++) {
                int r = sr + u * 32;
                uint32_t db = bb + (uint32_t)(r * 144 + ss * 16);
                int ko = (c + 1) * 64 + ss * 8;
                cpa16(db,           Ah + (size_t)(row0 + r) * K + ko);
                cpa16(db + PG_TILE, Bh + (size_t)(j0 + r) * K + ko);
            }
            asm volatile("cp.async.commit_group;" ::: "memory");
            asm volatile("cp.async.wait_group 1;" ::: "memory");
        } else {
            asm volatile("cp.async.wait_group 0;" ::: "memory");
        }
        __syncthreads();
        uint32_t bb = sb + (c & 1) * PG_BUF;
        #pragma unroll
        for (int ks = 0; ks < 4; ks++) {
            uint32_t ko = (uint32_t)(ks * 32);
            uint32_t ah[2][4], bh[4][4];
            #pragma unroll
            for (int mt = 0; mt < 2; mt++) {
                uint32_t a = bb + aoff + (uint32_t)(mt * 16 * 144) + ko;
                ldsm4(ah[mt][0], ah[mt][1], ah[mt][2], ah[mt][3], a);
            }
            #pragma unroll
            for (int p = 0; p < 4; p++) {
                uint32_t b = bb + PG_TILE + boff + (uint32_t)(p * 16 * 144) + ko;
                ldsm4(bh[p][0], bh[p][1], bh[p][2], bh[p][3], b);
            }
            #pragma unroll
            for (int p = 0; p < 4; p++)
                #pragma unroll
                for (int mt = 0; mt < 2; mt++) {
                    mma_f16(d[mt][2*p],   ah[mt], bh[p][0], bh[p][1]);
                    mma_f16(d[mt][2*p+1], ah[mt], bh[p][2], bh[p][3]);
                }
        }
        __syncthreads();
    }
}

// ---------------- K1: fused p1m + p2m -----------------------------------------
__global__ __launch_bounds__(256, 2) void p12_kernel(
        const float* __restrict__ bz, const float* __restrict__ br,
        const float* __restrict__ bn, const float* __restrict__ bgh) {
    extern __shared__ char smem[];
    uint32_t sb = smem_u32(smem);
    int tid = threadIdx.x;
    int row0 = blockIdx.y * 128;
    int wid = tid >> 5, l = tid & 31;
    int wr0 = (wid >> 1) * 32, wn0 = (wid & 1) * 64;
    float d[2][8][4];
    if (blockIdx.x < 12) {
        int s = blockIdx.x >> 2;
        int j0 = (blockIdx.x & 3) * 128;
        const float* bias = (s == 0) ? bz : (s == 1) ? br : bn;
        float* out = g_A + (size_t)s * TBH;
        pg_core<4>(sb, g_x1h, g_W1hh + (size_t)s * Hsz * 256, row0, j0, 256, tid, d);
        #pragma unroll
        for (int mt = 0; mt < 2; mt++)
            #pragma unroll
            for (int nf = 0; nf < 8; nf++)
                #pragma unroll
                for (int h = 0; h < 2; h++) {
                    int row = row0 + wr0 + mt * 16 + (l >> 2) + h * 8;
                    int col = j0 + wn0 + nf * 8 + (l & 3) * 2;
                    float2 v;
                    v.x = d[mt][nf][h * 2]     + bias[col];
                    v.y = d[mt][nf][h * 2 + 1] + bias[col + 1];
                    *(float2*)(out + (size_t)row * Hsz + col) = v;
                }
    } else {
        int j0 = (blockIdx.x - 12) * 128;
        pg_core<2>(sb, g_dh, g_Wghh, row0, j0, 128, tid, d);
        #pragma unroll
        for (int mt = 0; mt < 2; mt++)
            #pragma unroll
            for (int nf = 0; nf < 8; nf++)
                #pragma unroll
                for (int h = 0; h < 2; h++) {
                    int row = row0 + wr0 + mt * 16 + (l >> 2) + h * 8;
                    int col = j0 + wn0 + nf * 8 + (l & 3) * 2;
                    float2 v;
                    v.x = expf(-fmaxf(0.f, d[mt][nf][h * 2]     + bgh[col]));
                    v.y = expf(-fmaxf(0.f, d[mt][nf][h * 2 + 1] + bgh[col + 1]));
                    *(float2*)(g_gh + (size_t)row * Hsz + col) = v;
                }
    }
}

__global__ void dummy_kernel() {}

// ---------------- loop helpers ------------------------------------------------
__device__ __forceinline__ void stage32_issue(uint32_t A, const __half* __restrict__ gact,
                                              int r0, int tid) {
    #pragma unroll
    for (int u = 0; u < 4; u++) {
        int i = u * 512 + tid;
        cpa16(A + (uint32_t)((i >> 6) * 1040 + (i & 63) * 16),
              gact + (size_t)(r0 + (i >> 6)) * Hsz + (i & 63) * 8);
    }
    asm volatile("cp.async.commit_group;" ::: "memory");
}
__device__ __forceinline__ void stage_wait() {
    asm volatile("cp.async.wait_group 0;" ::: "memory");
    __syncthreads();
}

// 16x16 warp-tile fp16 GEMM over k range [k0, k0+KS*16); 8 accumulator chains
template<int KS>
__device__ __forceinline__ void mma_tileN2(uint32_t sb, uint32_t woff, int k0,
                                           int l, int wr0, int wn0, float d[2][4]) {
    uint32_t Ab = sb + OFF_ACT;
    uint32_t aoff = (uint32_t)((wr0 + (l & 15)) * 1040 + ((l >> 4) * 8) * 2 + k0 * 2);
    uint32_t b1o  = (uint32_t)((wn0 + (l & 7)) * 1040 + (l >> 3) * 16 + k0 * 2);
    uint32_t b2o  = b1o + 8 * 1040;
    float c[8][4];
    #pragma unroll
    for (int i = 0; i < 8; i++)
        #pragma unroll
        for (int j = 0; j < 4; j++) c[i][j] = 0.f;
    #pragma unroll
    for (int it = 0; it < KS / 2; it++) {
        uint32_t a0[4], a1[4], b1[4], b2[4];
        ldsm4(a0[0], a0[1], a0[2], a0[3], Ab + aoff + it * 64);
        ldsm4(a1[0], a1[1], a1[2], a1[3], Ab + aoff + it * 64 + 32);
        ldsm4(b1[0], b1[1], b1[2], b1[3], sb + woff + b1o + it * 64);
        ldsm4(b2[0], b2[1], b2[2], b2[3], sb + woff + b2o + it * 64);
        int p = (it & 1) * 4;
        mma_f16(c[p + 0], a0, b1[0], b1[1]);
        mma_f16(c[p + 1], a0, b2[0], b2[1]);
        mma_f16(c[p + 2], a1, b1[2], b1[3]);
        mma_f16(c[p + 3], a1, b2[2], b2[3]);
    }
    #pragma unroll
    for (int i = 0; i < 4; i++) {
        d[0][i] = (c[0][i] + c[2][i]) + (c[4][i] + c[6][i]);
        d[1][i] = (c[1][i] + c[3][i]) + (c[5][i] + c[7][i]);
    }
}

// 16x8 warp-tile fp16 GEMM (phase B), 4 accumulator chains
template<int KS>
__device__ __forceinline__ void mma_tile(uint32_t sb, uint32_t woff, int k0,
                                         int l, int wr0, int wn0, float d[4]) {
    uint32_t Ab = sb + OFF_ACT;
    uint32_t aoff = (uint32_t)((wr0 + (l & 15)) * 1040 + ((l >> 4) * 8) * 2 + k0 * 2);
    uint32_t boff = (uint32_t)((wn0 + (l & 7)) * 1040 + (l >> 3) * 16 + k0 * 2);
    float c0[4] = {0,0,0,0}, c1[4] = {0,0,0,0};
    float c2[4] = {0,0,0,0}, c3[4] = {0,0,0,0};
    #pragma unroll
    for (int it = 0; it < KS / 2; it++) {
        uint32_t a0[4], a1[4], b[4];
        ldsm4(a0[0], a0[1], a0[2], a0[3], Ab + aoff + it * 64);
        ldsm4(a1[0], a1[1], a1[2], a1[3], Ab + aoff + it * 64 + 32);
        ldsm4(b[0], b[1], b[2], b[3], sb + woff + boff + it * 64);
        if (it & 1) {
            mma_f16(c2, a0, b[0], b[1]);
            mma_f16(c3, a1, b[2], b[3]);
        } else {
            mma_f16(c0, a0, b[0], b[1]);
            mma_f16(c1, a1, b[2], b[3]);
        }
    }
    #pragma unroll
    for (int i = 0; i < 4; i++) d[i] = (c0[i] + c1[i]) + (c2[i] + c3[i]);
}

// ---------------- persistent recurrent loop kernel (512 thr, 2-group ilv) -----
__global__ __launch_bounds__(512, 1) void loop_kernel(float* __restrict__ out) {
    extern __shared__ char smem[];
    uint32_t sb = smem_u32(smem);
    int tid = threadIdx.x, cta = blockIdx.x;
    int wid = tid >> 5, l = tid & 31;

    int q = cta & 15;
    int gg0 = cta >> 4;                        // serves groups gg0 and gg0+8
    int sA  = q >> 3;                          // 0 = z, 1 = r
    int jA0 = (q & 7) * 64;
    int jB0 = q * 32;
    const __half* WAhi = g_Wh + (size_t)sA * Hsz * Hsz;
    const __half* WBhi = g_Wh + (size_t)2 * Hsz * Hsz;

    // one-time: hi weights into smem (1040B row stride)
    for (int i = tid; i < 4096; i += 512) {
        int r = i >> 6, s = i & 63;
        cpa16(sb + OFF_WA + r * 1040 + s * 16, WAhi + (size_t)(jA0 + r) * Hsz + s * 8);
    }
    for (int i = tid; i < 2048; i += 512) {
        int r = i >> 6, s = i & 63;
        cpa16(sb + OFF_WB + r * 1040 + s * 16, WBhi + (size_t)(jB0 + r) * Hsz + s * 8);
    }
    asm volatile("cp.async.commit_group;" ::: "memory");
    asm volatile("cp.async.wait_group 0;" ::: "memory");

    __half zh = __float2half(0.f);
    for (int i = tid; i < 2048; i += 512) {
        int o = cta * 2048 + i;
        g_HD[o] = 0.f;
        g_hd_h[o] = zh;
    }
    int grp[2] = {gg0, gg0 + 8};
    unsigned tg[2] = {16u, 16u};
    arrive_g(grp[0]);
    arrive_g(grp[1]);

    // phase A: 8 slots of 16x16 over 32x64, 2-way K-split (warps 8-15: k>=256)
    int widA = wid & 7;
    int wr0A = (widA & 1) * 16, wn0A = (widA >> 1) * 16;
    int kA0  = (wid < 8) ? 0 : 256;
    // phase B: 8 slots of 16x8 over 32x32, 2-way K-split
    int widB = wid & 7;
    int wr0B = (widB & 1) * 16, wn0B = (widB >> 1) * 8;
    int kB0  = (wid < 8) ? 0 : 256;

    for (int t = 0; t < Tsz; t++) {
        // ================== phase A for both groups ==========================
        #pragma unroll 1
        for (int pi = 0; pi < 2; pi++) {
            int g = grp[pi];
            int rA0 = g * 32;
            // barrier-INDEPENDENT prefetch (g_A is precomputed): issue pre-wait
            const float* At = g_A + (size_t)sA * TBH + (size_t)t * BH;
            float2 atv[2][2], hdv[2][2];
            if (wid < 8) {
                #pragma unroll
                for (int nf = 0; nf < 2; nf++)
                    #pragma unroll
                    for (int h = 0; h < 2; h++) {
                        int col = jA0 + wn0A + nf * 8 + (l & 3) * 2;
                        int row = rA0 + wr0A + (l >> 2) + h * 8;
                        atv[nf][h] = __ldcg((const float2*)(At + (size_t)row * Hsz + col));
                    }
            }
            wait_g(g, tg[pi]); tg[pi] += 16;
            stage32_issue(sb + OFF_ACT, g_hd_h, rA0, tid);
            if (wid < 8 && sA) {
                #pragma unroll
                for (int nf = 0; nf < 2; nf++)
                    #pragma unroll
                    for (int h = 0; h < 2; h++) {
                        int col = jA0 + wn0A + nf * 8 + (l & 3) * 2;
                        int row = rA0 + wr0A + (l >> 2) + h * 8;
                        hdv[nf][h] = __ldcg((const float2*)(g_HD + (size_t)row * Hsz + col));
                    }
            }
            stage_wait();
            float d[2][4];
            mma_tileN2<16>(sb, OFF_WA, kA0, l, wr0A, wn0A, d);
            if (wid >= 8) {
                uint32_t ra = sb + OFF_RED + (uint32_t)(widA * 1024 + l * 32);
                uint4 v0 = {__float_as_uint(d[0][0]), __float_as_uint(d[0][1]),
                            __float_as_uint(d[0][2]), __float_as_uint(d[0][3])};
                uint4 v1 = {__float_as_uint(d[1][0]), __float_as_uint(d[1][1]),
                            __float_as_uint(d[1][2]), __float_as_uint(d[1][3])};
                sts16(ra, v0);
                sts16(ra + 16, v1);
            }
            __syncthreads();
            if (wid < 8) {
                uint32_t off = OFF_RED + (uint32_t)(widA * 1024 + l * 32);
                uint4 v0 = *(const uint4*)(smem + off);
                uint4 v1 = *(const uint4*)(smem + off + 16);
                d[0][0] += __uint_as_float(v0.x); d[0][1] += __uint_as_float(v0.y);
                d[0][2] += __uint_as_float(v0.z); d[0][3] += __uint_as_float(v0.w);
                d[1][0] += __uint_as_float(v1.x); d[1][1] += __uint_as_float(v1.y);
                d[1][2] += __uint_as_float(v1.z); d[1][3] += __uint_as_float(v1.w);
                #pragma unroll
                for (int nf = 0; nf < 2; nf++) {
                    int col = jA0 + wn0A + nf * 8 + (l & 3) * 2;
                    #pragma unroll
                    for (int h = 0; h < 2; h++) {
                        int row = rA0 + wr0A + (l >> 2) + h * 8;
                        size_t o = (size_t)row * Hsz + col;
                        float s0 = sigm(d[nf][h * 2]     + atv[nf][h].x);
                        float s1 = sigm(d[nf][h * 2 + 1] + atv[nf][h].y);
                        if (sA == 0) {
                            float2 zz = {s0, s1};
                            *(float2*)(g_Z + o) = zz;
                        } else {
                            __half2 hp;
                            hp.x = __float2half(s0 * hdv[nf][h].x);
                            hp.y = __float2half(s1 * hdv[nf][h].y);
                            *(__half2*)(g_rh_h + o) = hp;
                        }
                    }
                }
            }
            arrive_g(g);
        }

        // ================== phase B for both groups ==========================
        #pragma unroll 1
        for (int pi = 0; pi < 2; pi++) {
            int g = grp[pi];
            int rB0 = g * 32;
            bool last = (t == Tsz - 1);
            int col = jB0 + wn0B + (l & 3) * 2;
            // barrier-INDEPENDENT prefetch: g_A (precomputed), g_gh
            // (precomputed), g_HD (written at B(t-1), ordered by A(t)'s wait
            // which this CTA already passed) -> all issue pre-wait.
            const float* An = g_A + (size_t)2 * TBH + (size_t)t * BH;
            const float* ghn = g_gh + (size_t)(t + 1) * BH;
            float2 anv[2], ghv[2], zv[2], hdv[2];
            if (wid < 8) {
                #pragma unroll
                for (int h = 0; h < 2; h++) {
                    int row = rB0 + wr0B + (l >> 2) + h * 8;
                    size_t o = (size_t)row * Hsz + col;
                    anv[h] = __ldcg((const float2*)(An + o));
                    hdv[h] = __ldcg((const float2*)(g_HD + o));
                    if (!last) ghv[h] = __ldcg((const float2*)(ghn + o));
                }
            }
            wait_g(g, tg[pi]); tg[pi] += 16;
            stage32_issue(sb + OFF_ACT, g_rh_h, rB0, tid);
            if (wid < 8) {
                #pragma unroll
                for (int h = 0; h < 2; h++) {
                    int row = rB0 + wr0B + (l >> 2) + h * 8;
                    size_t o = (size_t)row * Hsz + col;
                    zv[h] = __ldcg((const float2*)(g_Z + o));
                }
            }
            stage_wait();
            float d[4];
            mma_tile<16>(sb, OFF_WB, kB0, l, wr0B, wn0B, d);
            if (wid >= 8) {
                uint32_t ra = sb + OFF_RED + (uint32_t)(widB * 512 + l * 16);
                uint4 v = {__float_as_uint(d[0]), __float_as_uint(d[1]),
                           __float_as_uint(d[2]), __float_as_uint(d[3])};
                sts16(ra, v);
            }
            __syncthreads();
            if (wid < 8) {
                uint32_t off = OFF_RED + (uint32_t)(widB * 512 + l * 16);
                uint4 v = *(const uint4*)(smem + off);
                d[0] += __uint_as_float(v.x);
                d[1] += __uint_as_float(v.y);
                d[2] += __uint_as_float(v.z);
                d[3] += __uint_as_float(v.w);
                #pragma unroll
                for (int h = 0; h < 2; h++) {
                    int row = rB0 + wr0B + (l >> 2) + h * 8;
                    size_t o = (size_t)row * Hsz + col;
                    #pragma unroll
                    for (int q2 = 0; q2 < 2; q2++) {
                        float ht = tanhf(d[h * 2 + q2] + (q2 ? anv[h].y : anv[h].x));
                        float z  = q2 ? zv[h].y : zv[h].x;
                        float hd = q2 ? hdv[h].y : hdv[h].x;
                        float hp = (1.f - z) * hd + z * ht;
                        if (last) {
                            out[o + q2] = hp;
                        } else {
                            float hdn = (q2 ? ghv[h].y : ghv[h].x) * hp;
                            g_HD[o + q2] = hdn;
                            g_hd_h[o + q2] = __float2half(hdn);
                        }
                    }
                }
            }
            arrive_g(g);
        }
    }
}

// ---------------- launch ----------------
extern "C" void kernel_launch(void* const* d_in, const int* in_sizes, int n_in,
                              void* d_out, int out_size) {
    const float* x    = (const float*)d_in[0];
    const float* xl   = (const float*)d_in[1];
    const float* mk   = (const float*)d_in[2];
    const float* dl   = (const float*)d_in[3];
    const float* xm   = (const float*)d_in[4];
    const float* Wz   = (const float*)d_in[5];
    const float* bz   = (const float*)d_in[6];
    const float* Wr   = (const float*)d_in[7];
    const float* br   = (const float*)d_in[8];
    const float* Wn   = (const float*)d_in[9];
    const float* bn   = (const float*)d_in[10];
    const float* Wgx  = (const float*)d_in[11];
    const float* bgx  = (const float*)d_in[12];
    const float* Wgh  = (const float*)d_in[13];
    const float* bgh  = (const float*)d_in[14];

    static int smem_set = 0;
    if (!smem_set) {
        cudaFuncSetAttribute(loop_kernel,
                             cudaFuncAttributeMaxDynamicSharedMemorySize, SMEM_TOTAL);
        cudaFuncSetAttribute(p12_kernel,
                             cudaFuncAttributeMaxDynamicSharedMemorySize, PG_SMEM);
        smem_set = 1;
    }

    p0prep_kernel<<<65536 + 4864 + 1, 256>>>(x, xl, mk, dl, xm, Wgx, bgx,
                                             Wz, Wr, Wn, Wgh);
    p12_kernel<<<dim3(16, 1024), 256, PG_SMEM>>>(bz, br, bn, bgh);
    dummy_kernel<<<1, 32>>>();
    loop_kernel<<<NCTA, 512, SMEM_TOTAL>>>((float*)d_out);
}